// round 14
// baseline (speedup 1.0000x reference)
#include <cuda_runtime.h>

// Jacobi 5-iteration temporally-blocked cross stencil, sm_103a.
// R7 structure (rolling window, depth-2 rhs pipeline, rhs streamed from L2,
// no cross-barrier register liveness) at 4 CTAs/SM via NT=448.
// B=16, H=W=1024, radius-2 cross, boundary ring (width 2) frozen.

constexpr int HH  = 1024;
constexpr int WW  = 1024;
constexpr int NB  = 16;
constexpr int T   = 64;             // output tile
constexpr int RAD = 10;             // 2*5 halo
constexpr int L   = 84;             // local extent
constexpr int LP  = 84;             // stride
constexpr int NT  = 448;            // 14 warps; 4 CTAs/SM -> 56 warps
constexpr int SMEM_BYTES = (2 * L * LP + 4) * 4;   // 56,480 B; 4x = 225,920 <= 228K

template<bool EDGE>
__device__ __forceinline__ float4 rr_load(const float* __restrict__ rg,
                                          int gi, int gj)
{
    if (EDGE) {
        const bool ok = ((unsigned)gi < (unsigned)HH) && ((unsigned)gj < (unsigned)WW);
        return ok ? *(const float4*)(rg + (size_t)gi * WW + gj)
                  : make_float4(0.f, 0.f, 0.f, 0.f);
    }
    return *(const float4*)(rg + (size_t)gi * WW + gj);
}

// ---- middle sweeps: region [2,82)^2, 400 threads of 4x4 blocks, rolling ----
template<bool EDGE>
__device__ __forceinline__ void sweep_mid(const float* __restrict__ cur,
                                          float* __restrict__ nxt,
                                          const float* __restrict__ rg,
                                          int tid, int ti, int tj, float dinv,
                                          float k1x, float k2x, float k1y, float k2y)
{
    if (tid >= 400) return;
    const int rbk = tid / 20;
    const int cg  = tid - rbk * 20;
    const int li0 = 2 + 4 * rbk;
    const int lj  = 2 + 4 * cg;
    const int gi0 = ti + li0 - RAD;
    const int gj  = tj + lj - RAD;          // 4-aligned

    // depth-2 rhs pipeline
    float4 rrA = rr_load<EDGE>(rg, gi0 + 0, gj);
    float4 rrB = rr_load<EDGE>(rg, gi0 + 1, gj);

    const float* base = cur + li0 * LP + lj;
    float4 w0 = *(const float4*)(base - 2 * LP);
    float4 w1 = *(const float4*)(base - LP);
    float4 w2 = *(const float4*)(base);
    float4 w3 = *(const float4*)(base + LP);

    #pragma unroll
    for (int g = 0; g < 4; ++g) {
        const int li = li0 + g;
        const int gi = gi0 + g;
        const float4 w4 = *(const float4*)(base + (g + 2) * LP);
        const float2 hl = *(const float2*)(cur + li * LP + lj - 2);
        const float2 hr = *(const float2*)(cur + li * LP + lj + 4);

        const float4 rr = (g & 1) ? rrB : rrA;
        if (g == 0) rrA = rr_load<EDGE>(rg, gi0 + 2, gj);
        if (g == 1) rrB = rr_load<EDGE>(rg, gi0 + 3, gj);

        const float h0 = hl.x, h1 = hl.y, h2 = w2.x, h3 = w2.y;
        const float h4 = w2.z, h5 = w2.w, h6 = hr.x, h7 = hr.y;

        float4 o;
        o.x = fmaf(rr.x, dinv, -(k2x * (w0.x + w4.x) + k1x * (w1.x + w3.x)
                               + k2y * (h0 + h4) + k1y * (h1 + h3)));
        o.y = fmaf(rr.y, dinv, -(k2x * (w0.y + w4.y) + k1x * (w1.y + w3.y)
                               + k2y * (h1 + h5) + k1y * (h2 + h4)));
        o.z = fmaf(rr.z, dinv, -(k2x * (w0.z + w4.z) + k1x * (w1.z + w3.z)
                               + k2y * (h2 + h6) + k1y * (h3 + h5)));
        o.w = fmaf(rr.w, dinv, -(k2x * (w0.w + w4.w) + k1x * (w1.w + w3.w)
                               + k2y * (h3 + h7) + k1y * (h4 + h6)));

        if (EDGE) {
            const bool ir = (unsigned)(gi - 2) < (unsigned)(HH - 4);
            o.x = (ir && (unsigned)(gj + 0 - 2) < (unsigned)(WW - 4)) ? o.x : w2.x;
            o.y = (ir && (unsigned)(gj + 1 - 2) < (unsigned)(WW - 4)) ? o.y : w2.y;
            o.z = (ir && (unsigned)(gj + 2 - 2) < (unsigned)(WW - 4)) ? o.z : w2.z;
            o.w = (ir && (unsigned)(gj + 3 - 2) < (unsigned)(WW - 4)) ? o.w : w2.w;
        }
        *(float4*)(nxt + li * LP + lj) = o;

        w0 = w1; w1 = w2; w2 = w3; w3 = w4;
    }
}

// ---- final sweep: output [10,74)^2 as 1024 flat items (1 row x 4 cols),
//      stride NT so all 448 threads work; aligned STG.128 to global ----
template<bool EDGE>
__device__ __forceinline__ void sweep_last(const float* __restrict__ cur,
                                           const float* __restrict__ rg,
                                           float* __restrict__ ob,
                                           int tid, int ti, int tj, float dinv,
                                           float k1x, float k2x, float k1y, float k2y)
{
    constexpr int total = T * (T / 4);           // 1024
    #pragma unroll 2
    for (int idx = tid; idx < total; idx += NT) {
        const int li = RAD + (idx >> 4);
        const int lj = RAD + 4 * (idx & 15);
        const int gi = ti + li - RAD;            // in image
        const int gj = tj + lj - RAD;            // in image, 4-aligned

        const float* base = cur + li * LP + lj;
        const float4 rr = *(const float4*)(rg + (size_t)gi * WW + gj);
        const float4 w0 = *(const float4*)(base - 2 * LP);
        const float4 w1 = *(const float4*)(base - LP);
        const float4 w2 = *(const float4*)(base);
        const float4 w3 = *(const float4*)(base + LP);
        const float4 w4 = *(const float4*)(base + 2 * LP);
        const float2 hl = *(const float2*)(base - 2);
        const float2 hr = *(const float2*)(base + 4);

        const float h0 = hl.x, h1 = hl.y, h2 = w2.x, h3 = w2.y;
        const float h4 = w2.z, h5 = w2.w, h6 = hr.x, h7 = hr.y;

        float4 o;
        o.x = fmaf(rr.x, dinv, -(k2x * (w0.x + w4.x) + k1x * (w1.x + w3.x)
                               + k2y * (h0 + h4) + k1y * (h1 + h3)));
        o.y = fmaf(rr.y, dinv, -(k2x * (w0.y + w4.y) + k1x * (w1.y + w3.y)
                               + k2y * (h1 + h5) + k1y * (h2 + h4)));
        o.z = fmaf(rr.z, dinv, -(k2x * (w0.z + w4.z) + k1x * (w1.z + w3.z)
                               + k2y * (h2 + h6) + k1y * (h3 + h5)));
        o.w = fmaf(rr.w, dinv, -(k2x * (w0.w + w4.w) + k1x * (w1.w + w3.w)
                               + k2y * (h3 + h7) + k1y * (h4 + h6)));

        if (EDGE) {
            const bool ir = (unsigned)(gi - 2) < (unsigned)(HH - 4);
            o.x = (ir && (unsigned)(gj + 0 - 2) < (unsigned)(WW - 4)) ? o.x : w2.x;
            o.y = (ir && (unsigned)(gj + 1 - 2) < (unsigned)(WW - 4)) ? o.y : w2.y;
            o.z = (ir && (unsigned)(gj + 2 - 2) < (unsigned)(WW - 4)) ? o.z : w2.z;
            o.w = (ir && (unsigned)(gj + 3 - 2) < (unsigned)(WW - 4)) ? o.w : w2.w;
        }
        *(float4*)(ob + (size_t)gi * WW + gj) = o;
    }
}

template<bool EDGE>
__device__ __forceinline__ void run_all(float* A, float* Bf, const float* rg,
                                        float* ob, int tid, int ti, int tj, float dinv,
                                        float k1x, float k2x, float k1y, float k2y)
{
    sweep_mid<EDGE>(A,  Bf, rg, tid, ti, tj, dinv, k1x, k2x, k1y, k2y);
    __syncthreads();
    sweep_mid<EDGE>(Bf, A,  rg, tid, ti, tj, dinv, k1x, k2x, k1y, k2y);
    __syncthreads();
    sweep_mid<EDGE>(A,  Bf, rg, tid, ti, tj, dinv, k1x, k2x, k1y, k2y);
    __syncthreads();
    sweep_mid<EDGE>(Bf, A,  rg, tid, ti, tj, dinv, k1x, k2x, k1y, k2y);
    __syncthreads();
    sweep_last<EDGE>(A, rg, ob, tid, ti, tj, dinv, k1x, k2x, k1y, k2y);
}

__global__ void __launch_bounds__(NT, 4)
jacobi5_fused(const float* __restrict__ g0,
              const float* __restrict__ rhs,
              const float* __restrict__ dx,
              float* __restrict__ out)
{
    extern __shared__ float sm[];
    float* A  = sm + 2;             // +2-word shift: cols lj=2+4m are 16B aligned
    float* Bf = sm + 2 + L * LP;

    const int b  = blockIdx.z;
    const int ti = blockIdx.y * T;
    const int tj = blockIdx.x * T;

    const float ix = 1.0f / dx[2 * b + 0];
    const float iy = 1.0f / dx[2 * b + 1];
    const float sx = ix * ix;
    const float sy = iy * iy;
    const float dinv = 1.0f / (-2.5f * (sx + sy));
    const float k1x = dinv * sx * (4.0f / 3.0f);
    const float k2x = dinv * sx * (-1.0f / 12.0f);
    const float k1y = dinv * sy * (4.0f / 3.0f);
    const float k2y = dinv * sy * (-1.0f / 12.0f);

    const float* gb = g0  + (size_t)b * HH * WW;
    const float* rg = rhs + (size_t)b * HH * WW;
    float*       ob = out + (size_t)b * HH * WW;

    const int tid = threadIdx.x;
    const bool edge = (blockIdx.x == 0) | (blockIdx.x == gridDim.x - 1) |
                      (blockIdx.y == 0) | (blockIdx.y == gridDim.y - 1);

    // ---- load g halo into A ----
    if (edge) {
        for (int idx = tid; idx < L * L; idx += NT) {
            const int li = idx / L, lj = idx - (idx / L) * L;
            const int gi = ti + li - RAD, gj = tj + lj - RAD;
            float v = 0.0f;
            if (((unsigned)gi < (unsigned)HH) && ((unsigned)gj < (unsigned)WW))
                v = gb[(size_t)gi * WW + gj];
            A[li * LP + lj] = v;
        }
    } else {
        // float2-vectorized: 84 rows x 42 groups; gj even -> 8B aligned both sides
        constexpr int NGB = L / 2;                    // 42
        for (int idx = tid; idx < L * NGB; idx += NT) {
            const int li = idx / NGB, m = idx - (idx / NGB) * NGB;
            const int lj = 2 * m;
            const int gi = ti + li - RAD, gj = tj + lj - RAD;
            const float2 v = *(const float2*)(gb + (size_t)gi * WW + gj);
            *(float2*)(A + li * LP + lj) = v;
        }
    }
    __syncthreads();

    if (edge)
        run_all<true >(A, Bf, rg, ob, tid, ti, tj, dinv, k1x, k2x, k1y, k2y);
    else
        run_all<false>(A, Bf, rg, ob, tid, ti, tj, dinv, k1x, k2x, k1y, k2y);
}

extern "C" void kernel_launch(void* const* d_in, const int* in_sizes, int n_in,
                              void* d_out, int out_size) {
    const float* g0  = (const float*)d_in[0];
    const float* rhs = (const float*)d_in[1];
    const float* dx  = (const float*)d_in[2];
    float* out = (float*)d_out;

    cudaFuncSetAttribute(jacobi5_fused,
                         cudaFuncAttributeMaxDynamicSharedMemorySize, SMEM_BYTES);

    dim3 grid(WW / T, HH / T, NB);   // 16 x 16 x 16
    jacobi5_fused<<<grid, NT, SMEM_BYTES>>>(g0, rhs, dx, out);
}

// round 15
// speedup vs baseline: 1.0021x; 1.0021x over previous
#include <cuda_runtime.h>

// Jacobi 5-iteration temporally-blocked cross stencil, sm_103a.
// R7 structure (rolling window, depth-2 rhs pipeline, rhs streamed from L2,
// no cross-barrier register liveness) at 4 CTAs/SM via NT=448.
// B=16, H=W=1024, radius-2 cross, boundary ring (width 2) frozen.

constexpr int HH  = 1024;
constexpr int WW  = 1024;
constexpr int NB  = 16;
constexpr int T   = 64;             // output tile
constexpr int RAD = 10;             // 2*5 halo
constexpr int L   = 84;             // local extent
constexpr int LP  = 84;             // stride
constexpr int NT  = 448;            // 14 warps; 4 CTAs/SM -> 56 warps
constexpr int SMEM_BYTES = (2 * L * LP + 4) * 4;   // 56,480 B; 4x = 225,920 <= 228K

template<bool EDGE>
__device__ __forceinline__ float4 rr_load(const float* __restrict__ rg,
                                          int gi, int gj)
{
    if (EDGE) {
        const bool ok = ((unsigned)gi < (unsigned)HH) && ((unsigned)gj < (unsigned)WW);
        return ok ? *(const float4*)(rg + (size_t)gi * WW + gj)
                  : make_float4(0.f, 0.f, 0.f, 0.f);
    }
    return *(const float4*)(rg + (size_t)gi * WW + gj);
}

// ---- middle sweeps: region [2,82)^2, 400 threads of 4x4 blocks, rolling ----
template<bool EDGE>
__device__ __forceinline__ void sweep_mid(const float* __restrict__ cur,
                                          float* __restrict__ nxt,
                                          const float* __restrict__ rg,
                                          int tid, int ti, int tj, float dinv,
                                          float k1x, float k2x, float k1y, float k2y)
{
    if (tid >= 400) return;
    const int rbk = tid / 20;
    const int cg  = tid - rbk * 20;
    const int li0 = 2 + 4 * rbk;
    const int lj  = 2 + 4 * cg;
    const int gi0 = ti + li0 - RAD;
    const int gj  = tj + lj - RAD;          // 4-aligned

    // depth-2 rhs pipeline
    float4 rrA = rr_load<EDGE>(rg, gi0 + 0, gj);
    float4 rrB = rr_load<EDGE>(rg, gi0 + 1, gj);

    const float* base = cur + li0 * LP + lj;
    float4 w0 = *(const float4*)(base - 2 * LP);
    float4 w1 = *(const float4*)(base - LP);
    float4 w2 = *(const float4*)(base);
    float4 w3 = *(const float4*)(base + LP);

    #pragma unroll
    for (int g = 0; g < 4; ++g) {
        const int li = li0 + g;
        const int gi = gi0 + g;
        const float4 w4 = *(const float4*)(base + (g + 2) * LP);
        const float2 hl = *(const float2*)(cur + li * LP + lj - 2);
        const float2 hr = *(const float2*)(cur + li * LP + lj + 4);

        const float4 rr = (g & 1) ? rrB : rrA;
        if (g == 0) rrA = rr_load<EDGE>(rg, gi0 + 2, gj);
        if (g == 1) rrB = rr_load<EDGE>(rg, gi0 + 3, gj);

        const float h0 = hl.x, h1 = hl.y, h2 = w2.x, h3 = w2.y;
        const float h4 = w2.z, h5 = w2.w, h6 = hr.x, h7 = hr.y;

        float4 o;
        o.x = fmaf(rr.x, dinv, -(k2x * (w0.x + w4.x) + k1x * (w1.x + w3.x)
                               + k2y * (h0 + h4) + k1y * (h1 + h3)));
        o.y = fmaf(rr.y, dinv, -(k2x * (w0.y + w4.y) + k1x * (w1.y + w3.y)
                               + k2y * (h1 + h5) + k1y * (h2 + h4)));
        o.z = fmaf(rr.z, dinv, -(k2x * (w0.z + w4.z) + k1x * (w1.z + w3.z)
                               + k2y * (h2 + h6) + k1y * (h3 + h5)));
        o.w = fmaf(rr.w, dinv, -(k2x * (w0.w + w4.w) + k1x * (w1.w + w3.w)
                               + k2y * (h3 + h7) + k1y * (h4 + h6)));

        if (EDGE) {
            const bool ir = (unsigned)(gi - 2) < (unsigned)(HH - 4);
            o.x = (ir && (unsigned)(gj + 0 - 2) < (unsigned)(WW - 4)) ? o.x : w2.x;
            o.y = (ir && (unsigned)(gj + 1 - 2) < (unsigned)(WW - 4)) ? o.y : w2.y;
            o.z = (ir && (unsigned)(gj + 2 - 2) < (unsigned)(WW - 4)) ? o.z : w2.z;
            o.w = (ir && (unsigned)(gj + 3 - 2) < (unsigned)(WW - 4)) ? o.w : w2.w;
        }
        *(float4*)(nxt + li * LP + lj) = o;

        w0 = w1; w1 = w2; w2 = w3; w3 = w4;
    }
}

// ---- final sweep: output [10,74)^2 as 1024 flat items (1 row x 4 cols),
//      stride NT so all 448 threads work; aligned STG.128 to global ----
template<bool EDGE>
__device__ __forceinline__ void sweep_last(const float* __restrict__ cur,
                                           const float* __restrict__ rg,
                                           float* __restrict__ ob,
                                           int tid, int ti, int tj, float dinv,
                                           float k1x, float k2x, float k1y, float k2y)
{
    constexpr int total = T * (T / 4);           // 1024
    #pragma unroll 2
    for (int idx = tid; idx < total; idx += NT) {
        const int li = RAD + (idx >> 4);
        const int lj = RAD + 4 * (idx & 15);
        const int gi = ti + li - RAD;            // in image
        const int gj = tj + lj - RAD;            // in image, 4-aligned

        const float* base = cur + li * LP + lj;
        const float4 rr = *(const float4*)(rg + (size_t)gi * WW + gj);
        const float4 w0 = *(const float4*)(base - 2 * LP);
        const float4 w1 = *(const float4*)(base - LP);
        const float4 w2 = *(const float4*)(base);
        const float4 w3 = *(const float4*)(base + LP);
        const float4 w4 = *(const float4*)(base + 2 * LP);
        const float2 hl = *(const float2*)(base - 2);
        const float2 hr = *(const float2*)(base + 4);

        const float h0 = hl.x, h1 = hl.y, h2 = w2.x, h3 = w2.y;
        const float h4 = w2.z, h5 = w2.w, h6 = hr.x, h7 = hr.y;

        float4 o;
        o.x = fmaf(rr.x, dinv, -(k2x * (w0.x + w4.x) + k1x * (w1.x + w3.x)
                               + k2y * (h0 + h4) + k1y * (h1 + h3)));
        o.y = fmaf(rr.y, dinv, -(k2x * (w0.y + w4.y) + k1x * (w1.y + w3.y)
                               + k2y * (h1 + h5) + k1y * (h2 + h4)));
        o.z = fmaf(rr.z, dinv, -(k2x * (w0.z + w4.z) + k1x * (w1.z + w3.z)
                               + k2y * (h2 + h6) + k1y * (h3 + h5)));
        o.w = fmaf(rr.w, dinv, -(k2x * (w0.w + w4.w) + k1x * (w1.w + w3.w)
                               + k2y * (h3 + h7) + k1y * (h4 + h6)));

        if (EDGE) {
            const bool ir = (unsigned)(gi - 2) < (unsigned)(HH - 4);
            o.x = (ir && (unsigned)(gj + 0 - 2) < (unsigned)(WW - 4)) ? o.x : w2.x;
            o.y = (ir && (unsigned)(gj + 1 - 2) < (unsigned)(WW - 4)) ? o.y : w2.y;
            o.z = (ir && (unsigned)(gj + 2 - 2) < (unsigned)(WW - 4)) ? o.z : w2.z;
            o.w = (ir && (unsigned)(gj + 3 - 2) < (unsigned)(WW - 4)) ? o.w : w2.w;
        }
        *(float4*)(ob + (size_t)gi * WW + gj) = o;
    }
}

template<bool EDGE>
__device__ __forceinline__ void run_all(float* A, float* Bf, const float* rg,
                                        float* ob, int tid, int ti, int tj, float dinv,
                                        float k1x, float k2x, float k1y, float k2y)
{
    sweep_mid<EDGE>(A,  Bf, rg, tid, ti, tj, dinv, k1x, k2x, k1y, k2y);
    __syncthreads();
    sweep_mid<EDGE>(Bf, A,  rg, tid, ti, tj, dinv, k1x, k2x, k1y, k2y);
    __syncthreads();
    sweep_mid<EDGE>(A,  Bf, rg, tid, ti, tj, dinv, k1x, k2x, k1y, k2y);
    __syncthreads();
    sweep_mid<EDGE>(Bf, A,  rg, tid, ti, tj, dinv, k1x, k2x, k1y, k2y);
    __syncthreads();
    sweep_last<EDGE>(A, rg, ob, tid, ti, tj, dinv, k1x, k2x, k1y, k2y);
}

__global__ void __launch_bounds__(NT, 4)
jacobi5_fused(const float* __restrict__ g0,
              const float* __restrict__ rhs,
              const float* __restrict__ dx,
              float* __restrict__ out)
{
    extern __shared__ float sm[];
    float* A  = sm + 2;             // +2-word shift: cols lj=2+4m are 16B aligned
    float* Bf = sm + 2 + L * LP;

    const int b  = blockIdx.z;
    const int ti = blockIdx.y * T;
    const int tj = blockIdx.x * T;

    const float ix = 1.0f / dx[2 * b + 0];
    const float iy = 1.0f / dx[2 * b + 1];
    const float sx = ix * ix;
    const float sy = iy * iy;
    const float dinv = 1.0f / (-2.5f * (sx + sy));
    const float k1x = dinv * sx * (4.0f / 3.0f);
    const float k2x = dinv * sx * (-1.0f / 12.0f);
    const float k1y = dinv * sy * (4.0f / 3.0f);
    const float k2y = dinv * sy * (-1.0f / 12.0f);

    const float* gb = g0  + (size_t)b * HH * WW;
    const float* rg = rhs + (size_t)b * HH * WW;
    float*       ob = out + (size_t)b * HH * WW;

    const int tid = threadIdx.x;
    const bool edge = (blockIdx.x == 0) | (blockIdx.x == gridDim.x - 1) |
                      (blockIdx.y == 0) | (blockIdx.y == gridDim.y - 1);

    // ---- load g halo into A ----
    if (edge) {
        for (int idx = tid; idx < L * L; idx += NT) {
            const int li = idx / L, lj = idx - (idx / L) * L;
            const int gi = ti + li - RAD, gj = tj + lj - RAD;
            float v = 0.0f;
            if (((unsigned)gi < (unsigned)HH) && ((unsigned)gj < (unsigned)WW))
                v = gb[(size_t)gi * WW + gj];
            A[li * LP + lj] = v;
        }
    } else {
        // float2-vectorized: 84 rows x 42 groups; gj even -> 8B aligned both sides
        constexpr int NGB = L / 2;                    // 42
        for (int idx = tid; idx < L * NGB; idx += NT) {
            const int li = idx / NGB, m = idx - (idx / NGB) * NGB;
            const int lj = 2 * m;
            const int gi = ti + li - RAD, gj = tj + lj - RAD;
            const float2 v = *(const float2*)(gb + (size_t)gi * WW + gj);
            *(float2*)(A + li * LP + lj) = v;
        }
    }
    __syncthreads();

    if (edge)
        run_all<true >(A, Bf, rg, ob, tid, ti, tj, dinv, k1x, k2x, k1y, k2y);
    else
        run_all<false>(A, Bf, rg, ob, tid, ti, tj, dinv, k1x, k2x, k1y, k2y);
}

extern "C" void kernel_launch(void* const* d_in, const int* in_sizes, int n_in,
                              void* d_out, int out_size) {
    const float* g0  = (const float*)d_in[0];
    const float* rhs = (const float*)d_in[1];
    const float* dx  = (const float*)d_in[2];
    float* out = (float*)d_out;

    cudaFuncSetAttribute(jacobi5_fused,
                         cudaFuncAttributeMaxDynamicSharedMemorySize, SMEM_BYTES);

    dim3 grid(WW / T, HH / T, NB);   // 16 x 16 x 16
    jacobi5_fused<<<grid, NT, SMEM_BYTES>>>(g0, rhs, dx, out);
}